// round 7
// baseline (speedup 1.0000x reference)
#include <cuda_runtime.h>
#include <cuda_bf16.h>

// out[t,b,i,e] = x[t,b,i] * W[i,e] + b[e]
// T=8, B=64, D=512, E=256 -> 67,108,864 fp32 outputs (268 MB). Store-BW bound.
//
// R6 profile: dur 39.9us, DRAM 66%, L2 64%, L1 73% (hottest), issue 12.7%.
// Theory: L1 issue slots (store wavefront processing) are the most loaded
// stage. Use Blackwell 256-bit ld/st (v8.f32) to halve L1 slot consumption:
// one warp covers one full 1KB output row; each lane owns one 32-byte chunk
// (e = lane*8 .. lane*8+7): 1 LDG.256 (W) + 1 STG.256 per lane per row.
// 4 rows per warp -> 4 independent 256B-wide warp-stores in flight.
// __stcs-equivalent .cs policy keeps the write stream from evicting x/W/b.

#define D_DIM  512
#define NROWS  (8 * 64 * 512)            // 262144 rows
#define ROWS_PER_WARP 4
#define WARPS_PER_BLOCK 8
#define THREADS (WARPS_PER_BLOCK * 32)
#define NBLOCKS (NROWS / (ROWS_PER_WARP * WARPS_PER_BLOCK))   // 8192

__device__ __forceinline__ void ldg256(const float* p, float v[8]) {
    asm volatile("ld.global.nc.v8.f32 {%0,%1,%2,%3,%4,%5,%6,%7}, [%8];"
                 : "=f"(v[0]), "=f"(v[1]), "=f"(v[2]), "=f"(v[3]),
                   "=f"(v[4]), "=f"(v[5]), "=f"(v[6]), "=f"(v[7])
                 : "l"(p));
}

__device__ __forceinline__ void stg256_cs(float* p, const float v[8]) {
    asm volatile("st.global.cs.v8.f32 [%0], {%1,%2,%3,%4,%5,%6,%7,%8};"
                 :: "l"(p),
                    "f"(v[0]), "f"(v[1]), "f"(v[2]), "f"(v[3]),
                    "f"(v[4]), "f"(v[5]), "f"(v[6]), "f"(v[7])
                 : "memory");
}

__global__ __launch_bounds__(THREADS)
void dense_embed_kernel(const float* __restrict__ x,
                        const float* __restrict__ W,
                        const float* __restrict__ b,
                        float* __restrict__ out)
{
    unsigned warp_id = blockIdx.x * WARPS_PER_BLOCK + (threadIdx.x >> 5);
    unsigned lane    = threadIdx.x & 31;
    unsigned row0    = warp_id * ROWS_PER_WARP;
    unsigned eoff    = lane << 3;                 // lane*8 floats = 32B chunk

    float bb[8];
    ldg256(b + eoff, bb);

    // Front-batch all loads, then all stores.
    float xv[ROWS_PER_WARP];
    float wv[ROWS_PER_WARP][8];

    #pragma unroll
    for (int r = 0; r < ROWS_PER_WARP; ++r) {
        unsigned row = row0 + r;
        unsigned i   = row & (D_DIM - 1);         // row % 512
        xv[r] = __ldg(&x[row]);                   // uniform broadcast
        ldg256(W + (i << 8) + eoff, wv[r]);       // W row = 256 floats
    }

    #pragma unroll
    for (int r = 0; r < ROWS_PER_WARP; ++r) {
        float o[8];
        #pragma unroll
        for (int k = 0; k < 8; ++k)
            o[k] = fmaf(xv[r], wv[r][k], bb[k]);

        float* orow = out + (((unsigned long long)(row0 + r)) << 8);
        stg256_cs(orow + eoff, o);
    }
}

extern "C" void kernel_launch(void* const* d_in, const int* in_sizes, int n_in,
                              void* d_out, int out_size)
{
    const float* x = (const float*)d_in[0];
    const float* W = (const float*)d_in[1];
    const float* b = (const float*)d_in[2];
    float* out = (float*)d_out;

    dense_embed_kernel<<<NBLOCKS, THREADS>>>(x, W, b, out);
}